// round 6
// baseline (speedup 1.0000x reference)
#include <cuda_runtime.h>

#define BB 32
#define NN 1024
#define FF 128
#define HH 64
#define CC 32
#define KK 2
#define NITER 5
#define INV_TEMP 2.0f
#define ROWS (BB*NN)
#define FULLM 0xffffffffu
#define KC 64

typedef unsigned long long u64;

// packed fp32x2 FMA (2x fp32 throughput on sm_103a; ptxas never auto-emits)
#define FMA2(acc, a, b) asm("fma.rn.f32x2 %0, %1, %2, %0;" : "+l"(acc) : "l"(a), "l"(b))
__device__ __forceinline__ u64 pack2(float lo, float hi) {
    u64 r;
    asm("mov.b64 %0, {%1,%2};" : "=l"(r) : "r"(__float_as_uint(lo)), "r"(__float_as_uint(hi)));
    return r;
}
__device__ __forceinline__ u64 dup1(float v) {
    u64 r;
    asm("mov.b64 %0, {%1,%1};" : "=l"(r) : "r"(__float_as_uint(v)));
    return r;
}
__device__ __forceinline__ void unpack2(u64 v, float& lo, float& hi) {
    unsigned a, b;
    asm("mov.b64 {%0,%1}, %2;" : "=r"(a), "=r"(b) : "l"(v));
    lo = __uint_as_float(a); hi = __uint_as_float(b);
}

// ---------------- scratch (device globals; allocation-free) ----------------
__device__ float    g_dY[ROWS*HH];
__device__ float    g_dinv[ROWS];
__device__ unsigned g_adjb[ROWS*32];
__device__ unsigned g_adjl[ROWS*32];
__device__ int      g_nz[ROWS];
__device__ float    g_h[ROWS*HH];
__device__ float    g_unary[ROWS*CC];
__device__ float    g_e[ROWS*KK];
__device__ float    g_Qa[ROWS*CC];
__device__ float    g_AQ[ROWS*CC];
__device__ float    g_poolp[(size_t)BB*16*3072];

// ------------- K1: pack adjacency bits + degree -> dinv ---------------------
__global__ void k_bits(const int* __restrict__ adj) {
    int warp = threadIdx.x >> 5, lane = threadIdx.x & 31;
    int row  = blockIdx.x * 8 + warp;
    const int* ar = adj + (size_t)row * NN;
    unsigned myw = 0;
#pragma unroll
    for (int w = 0; w < 32; w++) {
        unsigned bal = __ballot_sync(FULLM, ar[(w << 5) + lane] != 0);
        if (lane == w) myw = bal;
    }
    g_adjb[row * 32 + lane] = myw;
    int d = __popc(myw);
#pragma unroll
    for (int o = 16; o; o >>= 1) d += __shfl_xor_sync(FULLM, d, o);
    if (lane == 0) g_dinv[row] = rsqrtf((float)d + 1.0f);
}

// ------------- K2: xw = x @ W_gcn, scaled by dinv ---------------------------
__global__ void k_xw(const float* __restrict__ x, const float* __restrict__ Wg) {
    __shared__ float Ws[FF * HH];
    for (int i = threadIdx.x; i < FF * HH; i += 256) Ws[i] = Wg[i];
    __syncthreads();
    int warp = threadIdx.x >> 5, lane = threadIdx.x & 31;
    for (int r = 0; r < 4; r++) {
        int row = blockIdx.x * 32 + warp * 4 + r;
        const float* xr = x + (size_t)row * FF;
        float a0 = 0.f, a1 = 0.f;
        for (int kb = 0; kb < FF; kb += 32) {
            float xv32 = xr[kb + lane];
#pragma unroll
            for (int t = 0; t < 32; t++) {
                float xv = __shfl_sync(FULLM, xv32, t);
                a0 += xv * Ws[(kb + t) * HH + lane];
                a1 += xv * Ws[(kb + t) * HH + lane + 32];
            }
        }
        float di = g_dinv[row];
        g_dY[(size_t)row * HH + lane]      = a0 * di;
        g_dY[(size_t)row * HH + lane + 32] = a1 * di;
    }
}

// ------------- K3: 2-hop reachability bitsets + zero counts -----------------
__global__ void k_adjl() {
    int warp = threadIdx.x >> 5, lane = threadIdx.x & 31;
    int row  = blockIdx.x * 8 + warp;
    int base = (row >> 10) << 10;
    unsigned myw = g_adjb[row * 32 + lane];
    unsigned acc = 0;
    for (int wk = 0; wk < 32; wk++) {
        unsigned bits = __shfl_sync(FULLM, myw, wk);
        while (bits) {
            int t = __ffs(bits) - 1; bits &= bits - 1;
            acc |= g_adjb[(size_t)(base + (wk << 5) + t) * 32 + lane];
        }
        if (__all_sync(FULLM, acc == FULLM)) break;
    }
    g_adjl[row * 32 + lane] = acc;
    int nz = __popc(~acc);
#pragma unroll
    for (int o = 16; o; o >>= 1) nz += __shfl_xor_sync(FULLM, nz, o);
    if (lane == 0) g_nz[row] = nz;
}

// ------------- K4: GCN aggregate, 256x64 tile, 8x8/thread fp32x2 ------------
// B stored ONCE (no dup), slot stride 12 words -> conflict-free; dup via MOV64.
__global__ void __launch_bounds__(256, 1) k_gcnagg_dense(const float* __restrict__ bg) {
    extern __shared__ float sm[];
    float* As = sm;                       // [KC][256]
    float* Bs = sm + KC * 256;            // [KC][96]  8 slots x 12 words
    int b = blockIdx.y, chunk = blockIdx.x;
    int tid = threadIdx.x;
    int tx = tid & 7, ty = tid >> 3;
    int rowbase = b * NN + chunk * 256;
    u64 acc[4][8];
#pragma unroll
    for (int i = 0; i < 4; i++)
#pragma unroll
        for (int j = 0; j < 8; j++) acc[i][j] = 0ull;

    const unsigned* abase = g_adjb + (size_t)rowbase * 32;

    // prefetch chunk 0
    unsigned nw0 = abase[(size_t)tid * 32];
    unsigned nw1 = abase[(size_t)tid * 32 + 1];
    float4 nb[4];
    {
        const float4* src = (const float4*)(g_dY + (size_t)(b * NN) * HH);
#pragma unroll
        for (int q = 0; q < 4; q++) nb[q] = src[tid + q * 256];
    }

    for (int kc = 0; kc < 16; kc++) {
        unsigned w0 = nw0, w1 = nw1;
        float4 vb[4] = { nb[0], nb[1], nb[2], nb[3] };
        __syncthreads();
#pragma unroll
        for (int bit = 0; bit < 32; bit++) {
            As[bit * 256 + tid]        = (float)((w0 >> bit) & 1);
            As[(32 + bit) * 256 + tid] = (float)((w1 >> bit) & 1);
        }
#pragma unroll
        for (int q = 0; q < 4; q++) {
            int j = tid + q * 256;
            int r = j >> 4, c4 = (j & 15) * 4;
            *(float4*)&Bs[r * 96 + (c4 >> 3) * 12 + (c4 & 7)] = vb[q];
        }
        if (kc < 15) {
            nw0 = abase[(size_t)tid * 32 + (kc + 1) * 2];
            nw1 = abase[(size_t)tid * 32 + (kc + 1) * 2 + 1];
            const float4* src = (const float4*)(g_dY + (size_t)(b * NN + (kc + 1) * 64) * HH);
#pragma unroll
            for (int q = 0; q < 4; q++) nb[q] = src[tid + q * 256];
        }
        __syncthreads();

#pragma unroll 4
        for (int k = 0; k < KC; k++) {
            float4 a0 = *(const float4*)&As[k * 256 + ty * 8];
            float4 a1 = *(const float4*)&As[k * 256 + ty * 8 + 4];
            u64 ap[4] = { pack2(a0.x, a0.y), pack2(a0.z, a0.w),
                          pack2(a1.x, a1.y), pack2(a1.z, a1.w) };
            const float* bp = &Bs[k * 96 + tx * 12];
            float4 b0 = *(const float4*)(bp);
            float4 b1 = *(const float4*)(bp + 4);
            u64 bq[8] = { dup1(b0.x), dup1(b0.y), dup1(b0.z), dup1(b0.w),
                          dup1(b1.x), dup1(b1.y), dup1(b1.z), dup1(b1.w) };
#pragma unroll
            for (int rp = 0; rp < 4; rp++)
#pragma unroll
                for (int c = 0; c < 8; c++)
                    FMA2(acc[rp][c], ap[rp], bq[c]);
        }
    }

    float4 bl = *(const float4*)&bg[tx * 8];
    float4 bh = *(const float4*)&bg[tx * 8 + 4];
#pragma unroll
    for (int rp = 0; rp < 4; rp++) {
        int r0 = rowbase + ty * 8 + rp * 2;
#pragma unroll
        for (int rr = 0; rr < 2; rr++) {
            int r = r0 + rr;
            float4 s0 = *(const float4*)&g_dY[(size_t)r * HH + tx * 8];
            float4 s1 = *(const float4*)&g_dY[(size_t)r * HH + tx * 8 + 4];
            float di = g_dinv[r];
            float o[8];
#pragma unroll
            for (int c = 0; c < 8; c++) {
                float lo, hi; unpack2(acc[rp][c], lo, hi);
                o[c] = rr ? hi : lo;
            }
            float4 h0, h1;
            h0.x = fmaxf(fmaf(o[0] + s0.x, di, bl.x), 0.f);
            h0.y = fmaxf(fmaf(o[1] + s0.y, di, bl.y), 0.f);
            h0.z = fmaxf(fmaf(o[2] + s0.z, di, bl.z), 0.f);
            h0.w = fmaxf(fmaf(o[3] + s0.w, di, bl.w), 0.f);
            h1.x = fmaxf(fmaf(o[4] + s1.x, di, bh.x), 0.f);
            h1.y = fmaxf(fmaf(o[5] + s1.y, di, bh.y), 0.f);
            h1.z = fmaxf(fmaf(o[6] + s1.z, di, bh.z), 0.f);
            h1.w = fmaxf(fmaf(o[7] + s1.w, di, bh.w), 0.f);
            *(float4*)&g_h[(size_t)r * HH + tx * 8]     = h0;
            *(float4*)&g_h[(size_t)r * HH + tx * 8 + 4] = h1;
        }
    }
}

// ------------- K5: unary + e + initial softmax ------------------------------
__global__ void k_unary_e(const float* __restrict__ Wu, const float* __restrict__ bu,
                          const float* __restrict__ means, const float* __restrict__ scales) {
    __shared__ float sW[HH * CC];
    __shared__ float sM[KK * HH], sS[KK * HH];
    for (int i = threadIdx.x; i < HH * CC; i += 256) sW[i] = Wu[i];
    for (int i = threadIdx.x; i < KK * HH; i += 256) { sM[i] = means[i]; sS[i] = scales[i]; }
    __syncthreads();
    int warp = threadIdx.x >> 5, lane = threadIdx.x & 31;
    int row  = blockIdx.x * 8 + warp;
    float h0 = g_h[(size_t)row * HH + lane];
    float h1 = g_h[(size_t)row * HH + lane + 32];
    float acc = bu[lane];
#pragma unroll
    for (int hh = 0; hh < HH; hh++) {
        float hv = __shfl_sync(FULLM, (hh < 32) ? h0 : h1, hh & 31);
        acc += hv * sW[hh * CC + lane];
    }
    g_unary[row * CC + lane] = acc;
#pragma unroll
    for (int k = 0; k < KK; k++) {
        float d0 = (h0 - sM[k * HH + lane])      / sS[k * HH + lane];
        float d1 = (h1 - sM[k * HH + lane + 32]) / sS[k * HH + lane + 32];
        float s = d0 * d0 + d1 * d1;
#pragma unroll
        for (int o = 16; o; o >>= 1) s += __shfl_xor_sync(FULLM, s, o);
        s = __shfl_sync(FULLM, s, 0);
        if (lane == 0) g_e[row * KK + k] = expf(-s);
    }
    float m = acc;
#pragma unroll
    for (int o = 16; o; o >>= 1) m = fmaxf(m, __shfl_xor_sync(FULLM, m, o));
    float ex = expf(acc - m);
    float s = ex;
#pragma unroll
    for (int o = 16; o; o >>= 1) s += __shfl_xor_sync(FULLM, s, o);
    g_Qa[row * CC + lane] = ex / s;
}

// ------------- K6: fused CRF, one block per batch, Q in smem ----------------
// colsum reordered: z_k = (sum_j e_jk Q_j) @ mu  (exact reassociation)
#define SMCRF ((NN*33 + NN*2 + 32*64 + 64 + CC*CC) * 4)
__global__ void __launch_bounds__(1024, 1) k_crf(const float* __restrict__ kw,
                                                 const float* __restrict__ mu) {
    extern __shared__ float s[];
    float* Qs   = s;                     // [1024*33] padded rows
    float* sE   = Qs + NN * 33;          // [1024*2]
    float* psum = sE + NN * 2;           // [32][64]
    float* scs  = psum + 32 * 64;        // [64]  (k*32+c)
    float* sMu  = scs + 64;              // [32*32]
    int b = blockIdx.x, t = threadIdx.x, warp = t >> 5, lane = t & 31;
    int row = b * NN + t;

    {   // load Q (coalesced) -> padded smem
        const float4* qsrc = (const float4*)(g_Qa + (size_t)b * NN * CC);
#pragma unroll
        for (int i = 0; i < 8; i++) {
            float4 v = qsrc[t * 8 + i];
            int o = t * 33 + i * 4;
            Qs[o] = v.x; Qs[o+1] = v.y; Qs[o+2] = v.z; Qs[o+3] = v.w;
        }
    }
    float my_e0 = g_e[row * 2], my_e1 = g_e[row * 2 + 1];
    sE[t * 2] = my_e0; sE[t * 2 + 1] = my_e1;
    if (t < CC * CC) sMu[t] = mu[t];
    float kw0 = kw[0], kw1 = kw[1];
    float E0 = my_e0 * kw0, E1 = my_e1 * kw1;
    int nz = g_nz[row];
    __syncthreads();

    for (int it = 0; it < NITER; it++) {
        // phase 1: per-warp e-weighted column sums of Q (rows warp*32..+31)
        float a0 = 0.f, a1 = 0.f;
        int r0 = warp * 32;
#pragma unroll 8
        for (int r = 0; r < 32; r++) {
            float q = Qs[(r0 + r) * 33 + lane];
            a0 = fmaf(sE[(r0 + r) * 2],     q, a0);
            a1 = fmaf(sE[(r0 + r) * 2 + 1], q, a1);
        }
        psum[warp * 64 + lane]      = a0;
        psum[warp * 64 + 32 + lane] = a1;
        __syncthreads();
        // phase 2+3: warps 0,1 reduce 32 partials, then @ mu -> cs[k][c]
        if (t < 64) {
            float tv = 0.f;
            for (int w = 0; w < 32; w++) tv += psum[w * 64 + warp * 32 + lane];
            float cs = 0.f;
#pragma unroll
            for (int i = 0; i < 32; i++) {
                float ti = __shfl_sync(FULLM, tv, i);
                cs = fmaf(ti, sMu[i * 32 + lane], cs);
            }
            scs[warp * 32 + lane] = cs;
        }
        __syncthreads();
        // phase 4: logits + softmax per row (thread-owned)
        float l[CC];
        const float4* urow = (const float4*)(g_unary + (size_t)row * CC);
#pragma unroll
        for (int i = 0; i < 8; i++) {
            float4 u = urow[i];
            l[i*4+0] = u.x + E0 * scs[i*4+0] + E1 * scs[32 + i*4+0];
            l[i*4+1] = u.y + E0 * scs[i*4+1] + E1 * scs[32 + i*4+1];
            l[i*4+2] = u.z + E0 * scs[i*4+2] + E1 * scs[32 + i*4+2];
            l[i*4+3] = u.w + E0 * scs[i*4+3] + E1 * scs[32 + i*4+3];
        }
        if (nz > 0) {   // complement correction (statistically never taken)
            for (int w = 0; w < 32; w++) {
                unsigned zb = ~g_adjl[(size_t)row * 32 + w];
                while (zb) {
                    int j = __ffs(zb) - 1; zb &= zb - 1;
                    int jl = w * 32 + j;
                    float w2 = E0 * sE[jl * 2] + E1 * sE[jl * 2 + 1];
#pragma unroll
                    for (int c = 0; c < CC; c++) {
                        float p = 0.f;
                        for (int i = 0; i < CC; i++)
                            p = fmaf(Qs[jl * 33 + i], sMu[i * 32 + c], p);
                        l[c] -= w2 * p;
                    }
                }
            }
        }
        float m = -1e30f;
#pragma unroll
        for (int c = 0; c < CC; c++) { l[c] *= INV_TEMP; m = fmaxf(m, l[c]); }
        float ssum = 0.f;
#pragma unroll
        for (int c = 0; c < CC; c++) { l[c] = expf(l[c] - m); ssum += l[c]; }
        float inv = 1.f / ssum;
        __syncthreads();            // all corrections read old Qs
#pragma unroll
        for (int c = 0; c < CC; c++) Qs[t * 33 + c] = l[c] * inv;
        __syncthreads();
    }
    {   // writeback final Q
        float4* qdst = (float4*)(g_Qa + (size_t)b * NN * CC);
#pragma unroll
        for (int i = 0; i < 8; i++) {
            int o = t * 33 + i * 4;
            qdst[t * 8 + i] = make_float4(Qs[o], Qs[o+1], Qs[o+2], Qs[o+3]);
        }
    }
}

// ------------- K7: AQ = adj @ Q, 256x32 tile, 8x4/thread fp32x2 -------------
__global__ void __launch_bounds__(256, 1) k_AQ_dense() {
    extern __shared__ float sm[];
    float* As = sm;                       // [KC][256]
    float* Bs = sm + KC * 256;            // [KC][96]  8 slots x 12 words (4 used)
    int b = blockIdx.y, chunk = blockIdx.x;
    int tid = threadIdx.x;
    int tx = tid & 7, ty = tid >> 3;
    int rowbase = b * NN + chunk * 256;
    u64 acc[4][4];
#pragma unroll
    for (int i = 0; i < 4; i++)
#pragma unroll
        for (int j = 0; j < 4; j++) acc[i][j] = 0ull;

    const unsigned* abase = g_adjb + (size_t)rowbase * 32;

    unsigned nw0 = abase[(size_t)tid * 32];
    unsigned nw1 = abase[(size_t)tid * 32 + 1];
    float4 nb[2];
    {
        const float4* src = (const float4*)(g_Qa + (size_t)(b * NN) * CC);
#pragma unroll
        for (int q = 0; q < 2; q++) nb[q] = src[tid + q * 256];
    }

    for (int kc = 0; kc < 16; kc++) {
        unsigned w0 = nw0, w1 = nw1;
        float4 vb[2] = { nb[0], nb[1] };
        __syncthreads();
#pragma unroll
        for (int bit = 0; bit < 32; bit++) {
            As[bit * 256 + tid]        = (float)((w0 >> bit) & 1);
            As[(32 + bit) * 256 + tid] = (float)((w1 >> bit) & 1);
        }
#pragma unroll
        for (int q = 0; q < 2; q++) {
            int j = tid + q * 256;
            int r = j >> 3, c4 = (j & 7) * 4;
            *(float4*)&Bs[r * 96 + (c4 >> 2) * 12] = vb[q];
        }
        if (kc < 15) {
            nw0 = abase[(size_t)tid * 32 + (kc + 1) * 2];
            nw1 = abase[(size_t)tid * 32 + (kc + 1) * 2 + 1];
            const float4* src = (const float4*)(g_Qa + (size_t)(b * NN + (kc + 1) * 64) * CC);
#pragma unroll
            for (int q = 0; q < 2; q++) nb[q] = src[tid + q * 256];
        }
        __syncthreads();

#pragma unroll 4
        for (int k = 0; k < KC; k++) {
            float4 a0 = *(const float4*)&As[k * 256 + ty * 8];
            float4 a1 = *(const float4*)&As[k * 256 + ty * 8 + 4];
            u64 ap[4] = { pack2(a0.x, a0.y), pack2(a0.z, a0.w),
                          pack2(a1.x, a1.y), pack2(a1.z, a1.w) };
            float4 b0 = *(const float4*)&Bs[k * 96 + tx * 12];
            u64 bq[4] = { dup1(b0.x), dup1(b0.y), dup1(b0.z), dup1(b0.w) };
#pragma unroll
            for (int rp = 0; rp < 4; rp++)
#pragma unroll
                for (int c = 0; c < 4; c++)
                    FMA2(acc[rp][c], ap[rp], bq[c]);
        }
    }

#pragma unroll
    for (int rp = 0; rp < 4; rp++) {
        int r0 = rowbase + ty * 8 + rp * 2;
        float o0[4], o1[4];
#pragma unroll
        for (int c = 0; c < 4; c++) unpack2(acc[rp][c], o0[c], o1[c]);
        *(float4*)&g_AQ[(size_t)r0 * CC + tx * 4]       = make_float4(o0[0], o0[1], o0[2], o0[3]);
        *(float4*)&g_AQ[(size_t)(r0 + 1) * CC + tx * 4] = make_float4(o1[0], o1[1], o1[2], o1[3]);
    }
}

// ------------- K8a: pooled outputs, N-split partials ------------------------
__global__ void k_poolp() {
    __shared__ float Qs[64 * 32];
    __shared__ float hs[64 * 64];
    __shared__ float Aq[64 * 32];
    int b = blockIdx.x, nc = blockIdx.y;
    int tid = threadIdx.x;                  // 256
    int n0 = b * NN + nc * 64;
    {
        const float4* sq = (const float4*)(g_Qa + (size_t)n0 * CC);
        const float4* sh = (const float4*)(g_h  + (size_t)n0 * HH);
        const float4* sa = (const float4*)(g_AQ + (size_t)n0 * CC);
        ((float4*)Qs)[tid] = sq[tid];  ((float4*)Qs)[tid + 256] = sq[tid + 256];
        ((float4*)Aq)[tid] = sa[tid];  ((float4*)Aq)[tid + 256] = sa[tid + 256];
#pragma unroll
        for (int q = 0; q < 4; q++) ((float4*)hs)[tid + q * 256] = sh[tid + q * 256];
    }
    __syncthreads();
    int tx = tid & 15, ty = tid >> 4;
    float xp[2][4] = {};
    float ap[2][2] = {};
    for (int n = 0; n < 64; n++) {
        float q0 = Qs[n * 32 + ty * 2], q1 = Qs[n * 32 + ty * 2 + 1];
        float4 hv = *(const float4*)&hs[n * 64 + tx * 4];
        float a0 = Aq[n * 32 + tx * 2], a1 = Aq[n * 32 + tx * 2 + 1];
        xp[0][0] += q0 * hv.x; xp[0][1] += q0 * hv.y; xp[0][2] += q0 * hv.z; xp[0][3] += q0 * hv.w;
        xp[1][0] += q1 * hv.x; xp[1][1] += q1 * hv.y; xp[1][2] += q1 * hv.z; xp[1][3] += q1 * hv.w;
        ap[0][0] += q0 * a0; ap[0][1] += q0 * a1;
        ap[1][0] += q1 * a0; ap[1][1] += q1 * a1;
    }
    float* dst = g_poolp + ((size_t)b * 16 + nc) * 3072;
#pragma unroll
    for (int cc = 0; cc < 2; cc++) {
#pragma unroll
        for (int c4 = 0; c4 < 4; c4++)
            dst[(ty * 2 + cc) * 64 + tx * 4 + c4] = xp[cc][c4];
#pragma unroll
        for (int a = 0; a < 2; a++)
            dst[2048 + (ty * 2 + cc) * 32 + tx * 2 + a] = ap[cc][a];
    }
}

// ------------- K8b: reduce pooling partials ---------------------------------
__global__ void k_poolred(float* __restrict__ out) {
    int b = blockIdx.x;
    int idx = blockIdx.y * 256 + threadIdx.x;
    float s = 0.f;
    for (int ch = 0; ch < 16; ch++) s += g_poolp[((size_t)b * 16 + ch) * 3072 + idx];
    if (idx < 2048) {
        int c = idx >> 6, hcol = idx & 63;
        out[((size_t)b * CC + c) * HH + hcol] = s;
    } else {
        int j = idx - 2048, c = j >> 5, a = j & 31;
        out[(size_t)BB * CC * HH + ((size_t)b * CC + c) * CC + a] = s;
    }
}

// ---------------------------------------------------------------------------
extern "C" void kernel_launch(void* const* d_in, const int* in_sizes, int n_in,
                              void* d_out, int out_size) {
    const float* x      = (const float*)d_in[0];
    const int*   adj    = (const int*)  d_in[1];
    const float* Wg     = (const float*)d_in[2];
    const float* bg     = (const float*)d_in[3];
    const float* Wu     = (const float*)d_in[4];
    const float* bu     = (const float*)d_in[5];
    const float* means  = (const float*)d_in[6];
    const float* scales = (const float*)d_in[7];
    const float* kw     = (const float*)d_in[8];
    const float* mu     = (const float*)d_in[9];
    float* out = (float*)d_out;

    const int SMG = (KC * 256 + KC * 96) * 4;   // 90112 B
    cudaFuncSetAttribute(k_gcnagg_dense, cudaFuncAttributeMaxDynamicSharedMemorySize, SMG);
    cudaFuncSetAttribute(k_AQ_dense,     cudaFuncAttributeMaxDynamicSharedMemorySize, SMG);
    cudaFuncSetAttribute(k_crf,          cudaFuncAttributeMaxDynamicSharedMemorySize, SMCRF);

    k_bits        <<<ROWS / 8,  256>>>(adj);
    k_xw          <<<ROWS / 32, 256>>>(x, Wg);
    k_adjl        <<<ROWS / 8,  256>>>();
    k_gcnagg_dense<<<dim3(4, BB), 256, SMG>>>(bg);
    k_unary_e     <<<ROWS / 8,  256>>>(Wu, bu, means, scales);
    k_crf         <<<BB, 1024, SMCRF>>>(kw, mu);
    k_AQ_dense    <<<dim3(4, BB), 256, SMG>>>();
    k_poolp       <<<dim3(BB, 16), 256>>>();
    k_poolred     <<<dim3(BB, 12), 256>>>(out);
}

// round 7
// speedup vs baseline: 1.3141x; 1.3141x over previous
#include <cuda_runtime.h>

#define BB 32
#define NN 1024
#define FF 128
#define HH 64
#define CC 32
#define KK 2
#define NITER 5
#define INV_TEMP 2.0f
#define ROWS (BB*NN)
#define FULLM 0xffffffffu
#define KC 64

// padded duplicated-B strides (bank-conflict-free across tx)
#define BSTRIDE_G 160   // gcnagg: 8 tx slots * 20 words
#define BSLOT_G   20
#define BSTRIDE_A 96    // AQ: 8 tx slots * 12 words
#define BSLOT_A   12

typedef unsigned long long u64;

// packed fp32x2 FMA (2x fp32 throughput on sm_103a; ptxas never auto-emits)
#define FMA2(acc, a, b) asm("fma.rn.f32x2 %0, %1, %2, %0;" : "+l"(acc) : "l"(a), "l"(b))
__device__ __forceinline__ u64 pack2(float lo, float hi) {
    u64 r;
    asm("mov.b64 %0, {%1,%2};" : "=l"(r) : "r"(__float_as_uint(lo)), "r"(__float_as_uint(hi)));
    return r;
}
__device__ __forceinline__ void unpack2(u64 v, float& lo, float& hi) {
    unsigned a, b;
    asm("mov.b64 {%0,%1}, %2;" : "=r"(a), "=r"(b) : "l"(v));
    lo = __uint_as_float(a); hi = __uint_as_float(b);
}

// ---------------- scratch (device globals; allocation-free) ----------------
__device__ float    g_dY[ROWS*HH];
__device__ float    g_dinv[ROWS];
__device__ unsigned g_adjb[ROWS*32];
__device__ unsigned g_adjl[ROWS*32];
__device__ float    g_h[ROWS*HH];
__device__ float    g_unary[ROWS*CC];
__device__ float    g_e[ROWS*KK];
__device__ float    g_Qa[ROWS*CC];
__device__ float    g_Qb[ROWS*CC];
__device__ float    g_cs[BB*64];
__device__ float    g_AQ[ROWS*CC];
__device__ float    g_poolp[(size_t)BB*16*3072];

__device__ __forceinline__ const float* qsel(int s) { return s ? g_Qb : g_Qa; }
__device__ __forceinline__ float*       qselw(int s){ return s ? g_Qb : g_Qa; }

// ------------- K1: pack adjacency bits + degree -> dinv ---------------------
__global__ void k_bits(const int* __restrict__ adj) {
    int warp = threadIdx.x >> 5, lane = threadIdx.x & 31;
    int row  = blockIdx.x * 8 + warp;
    const int* ar = adj + (size_t)row * NN;
    unsigned myw = 0;
#pragma unroll
    for (int w = 0; w < 32; w++) {
        unsigned bal = __ballot_sync(FULLM, ar[(w << 5) + lane] != 0);
        if (lane == w) myw = bal;
    }
    g_adjb[row * 32 + lane] = myw;
    int d = __popc(myw);
#pragma unroll
    for (int o = 16; o; o >>= 1) d += __shfl_xor_sync(FULLM, d, o);
    if (lane == 0) g_dinv[row] = rsqrtf((float)d + 1.0f);
}

// ------------- K2: xw = x @ W_gcn, scaled by dinv ---------------------------
__global__ void k_xw(const float* __restrict__ x, const float* __restrict__ Wg) {
    __shared__ float Ws[FF * HH];
    for (int i = threadIdx.x; i < FF * HH; i += 256) Ws[i] = Wg[i];
    __syncthreads();
    int warp = threadIdx.x >> 5, lane = threadIdx.x & 31;
    for (int r = 0; r < 4; r++) {
        int row = blockIdx.x * 32 + warp * 4 + r;
        const float* xr = x + (size_t)row * FF;
        float a0 = 0.f, a1 = 0.f;
        for (int kb = 0; kb < FF; kb += 32) {
            float xv32 = xr[kb + lane];
#pragma unroll
            for (int t = 0; t < 32; t++) {
                float xv = __shfl_sync(FULLM, xv32, t);
                a0 += xv * Ws[(kb + t) * HH + lane];
                a1 += xv * Ws[(kb + t) * HH + lane + 32];
            }
        }
        float di = g_dinv[row];
        g_dY[(size_t)row * HH + lane]      = a0 * di;
        g_dY[(size_t)row * HH + lane + 32] = a1 * di;
    }
}

// ------------- K3: 2-hop reachability bitsets -------------------------------
__global__ void k_adjl() {
    int warp = threadIdx.x >> 5, lane = threadIdx.x & 31;
    int row  = blockIdx.x * 8 + warp;
    int base = (row >> 10) << 10;
    unsigned myw = g_adjb[row * 32 + lane];
    unsigned acc = 0;
    for (int wk = 0; wk < 32; wk++) {
        unsigned bits = __shfl_sync(FULLM, myw, wk);
        while (bits) {
            int t = __ffs(bits) - 1; bits &= bits - 1;
            acc |= g_adjb[(size_t)(base + (wk << 5) + t) * 32 + lane];
        }
        if (__all_sync(FULLM, acc == FULLM)) break;
    }
    g_adjl[row * 32 + lane] = acc;
}

// ------------- K4: GCN aggregate, 256x64 tile, 8x8/thread fp32x2 ------------
// (EXACT round-5 body: duplicated-B in padded smem; known-good FFMA2 codegen)
__global__ void __launch_bounds__(256, 1) k_gcnagg_dense(const float* __restrict__ bg) {
    extern __shared__ float sm[];
    float* As  = sm;                      // [KC][256]
    float* Bs2 = sm + KC * 256;           // [KC][BSTRIDE_G] duplicated, padded
    int b = blockIdx.y, chunk = blockIdx.x;
    int tid = threadIdx.x;
    int tx = tid & 7, ty = tid >> 3;      // tx: 8 cols, ty: 8 rows
    int rowbase = b * NN + chunk * 256;
    u64 acc[4][8];
#pragma unroll
    for (int i = 0; i < 4; i++)
#pragma unroll
        for (int j = 0; j < 8; j++) acc[i][j] = 0ull;

    const unsigned* abase = g_adjb + (size_t)rowbase * 32;

    for (int kc = 0; kc < 16; kc++) {
        __syncthreads();
        // expand A bits: thread t handles tile-row t, 64 k-bits
        unsigned w0 = abase[(size_t)tid * 32 + kc * 2];
        unsigned w1 = abase[(size_t)tid * 32 + kc * 2 + 1];
#pragma unroll
        for (int bit = 0; bit < 32; bit++) {
            As[bit * 256 + tid]        = (float)((w0 >> bit) & 1);
            As[(32 + bit) * 256 + tid] = (float)((w1 >> bit) & 1);
        }
        // stage B (dY rows kc*64..+64, 64 cols) duplicated (b,b), padded slots
        {
            const float4* src = (const float4*)(g_dY + (size_t)(b * NN + kc * 64) * HH);
#pragma unroll
            for (int q = 0; q < 4; q++) {
                int j = tid + q * 256;               // 1024 float4s
                float4 v = src[j];
                int r = j >> 4, c4 = (j & 15) * 4;   // cols c4..c4+3 (same 8-group)
                int g = c4 >> 3, wc = c4 & 7;
                float* dst = &Bs2[r * BSTRIDE_G + g * BSLOT_G + wc * 2];
                *(float4*)(dst)     = make_float4(v.x, v.x, v.y, v.y);
                *(float4*)(dst + 4) = make_float4(v.z, v.z, v.w, v.w);
            }
        }
        __syncthreads();

#pragma unroll 4
        for (int k = 0; k < KC; k++) {
            float4 a0 = *(const float4*)&As[k * 256 + ty * 8];
            float4 a1 = *(const float4*)&As[k * 256 + ty * 8 + 4];
            u64 ap[4] = { pack2(a0.x, a0.y), pack2(a0.z, a0.w),
                          pack2(a1.x, a1.y), pack2(a1.z, a1.w) };
            const float* bp = &Bs2[k * BSTRIDE_G + tx * BSLOT_G];
            float4 b0 = *(const float4*)(bp);
            float4 b1 = *(const float4*)(bp + 4);
            float4 b2 = *(const float4*)(bp + 8);
            float4 b3 = *(const float4*)(bp + 12);
            u64 bq[8] = { pack2(b0.x, b0.y), pack2(b0.z, b0.w),
                          pack2(b1.x, b1.y), pack2(b1.z, b1.w),
                          pack2(b2.x, b2.y), pack2(b2.z, b2.w),
                          pack2(b3.x, b3.y), pack2(b3.z, b3.w) };
#pragma unroll
            for (int rp = 0; rp < 4; rp++)
#pragma unroll
                for (int c = 0; c < 8; c++)
                    FMA2(acc[rp][c], ap[rp], bq[c]);
        }
    }

    // epilogue: h = relu(dinv_i*(C + dY_i) + bias)
    float4 bl = *(const float4*)&bg[tx * 8];
    float4 bh = *(const float4*)&bg[tx * 8 + 4];
#pragma unroll
    for (int rp = 0; rp < 4; rp++) {
        int r0 = rowbase + ty * 8 + rp * 2;
#pragma unroll
        for (int rr = 0; rr < 2; rr++) {
            int r = r0 + rr;
            float4 s0 = *(const float4*)&g_dY[(size_t)r * HH + tx * 8];
            float4 s1 = *(const float4*)&g_dY[(size_t)r * HH + tx * 8 + 4];
            float di = g_dinv[r];
            float o[8];
#pragma unroll
            for (int c = 0; c < 8; c++) {
                float lo, hi; unpack2(acc[rp][c], lo, hi);
                o[c] = rr ? hi : lo;
            }
            float4 h0, h1;
            h0.x = fmaxf(fmaf(o[0] + s0.x, di, bl.x), 0.f);
            h0.y = fmaxf(fmaf(o[1] + s0.y, di, bl.y), 0.f);
            h0.z = fmaxf(fmaf(o[2] + s0.z, di, bl.z), 0.f);
            h0.w = fmaxf(fmaf(o[3] + s0.w, di, bl.w), 0.f);
            h1.x = fmaxf(fmaf(o[4] + s1.x, di, bh.x), 0.f);
            h1.y = fmaxf(fmaf(o[5] + s1.y, di, bh.y), 0.f);
            h1.z = fmaxf(fmaf(o[6] + s1.z, di, bh.z), 0.f);
            h1.w = fmaxf(fmaf(o[7] + s1.w, di, bh.w), 0.f);
            *(float4*)&g_h[(size_t)r * HH + tx * 8]     = h0;
            *(float4*)&g_h[(size_t)r * HH + tx * 8 + 4] = h1;
        }
    }
}

// ------------- K5: unary + e + initial softmax ------------------------------
__global__ void k_unary_e(const float* __restrict__ Wu, const float* __restrict__ bu,
                          const float* __restrict__ means, const float* __restrict__ scales) {
    __shared__ float sW[HH * CC];
    __shared__ float sM[KK * HH], sS[KK * HH];
    for (int i = threadIdx.x; i < HH * CC; i += 256) sW[i] = Wu[i];
    for (int i = threadIdx.x; i < KK * HH; i += 256) { sM[i] = means[i]; sS[i] = scales[i]; }
    __syncthreads();
    int warp = threadIdx.x >> 5, lane = threadIdx.x & 31;
    int row  = blockIdx.x * 8 + warp;
    float h0 = g_h[(size_t)row * HH + lane];
    float h1 = g_h[(size_t)row * HH + lane + 32];
    float acc = bu[lane];
#pragma unroll
    for (int hh = 0; hh < HH; hh++) {
        float hv = __shfl_sync(FULLM, (hh < 32) ? h0 : h1, hh & 31);
        acc += hv * sW[hh * CC + lane];
    }
    g_unary[row * CC + lane] = acc;
#pragma unroll
    for (int k = 0; k < KK; k++) {
        float d0 = (h0 - sM[k * HH + lane])      / sS[k * HH + lane];
        float d1 = (h1 - sM[k * HH + lane + 32]) / sS[k * HH + lane + 32];
        float s = d0 * d0 + d1 * d1;
#pragma unroll
        for (int o = 16; o; o >>= 1) s += __shfl_xor_sync(FULLM, s, o);
        s = __shfl_sync(FULLM, s, 0);
        if (lane == 0) g_e[row * KK + k] = expf(-s);
    }
    float m = acc;
#pragma unroll
    for (int o = 16; o; o >>= 1) m = fmaxf(m, __shfl_xor_sync(FULLM, m, o));
    float ex = expf(acc - m);
    float s = ex;
#pragma unroll
    for (int o = 16; o; o >>= 1) s += __shfl_xor_sync(FULLM, s, o);
    g_Qa[row * CC + lane] = ex / s;
}

// ------------- CRF part 1: cs[k][c] = (sum_j e_jk Q_j) @ mu  (reassociated) --
__global__ void k_cs2(const float* __restrict__ mu, int sel) {
    const float* Qb = qsel(sel) + (size_t)blockIdx.x * NN * CC;
    const float* eb = g_e       + (size_t)blockIdx.x * NN * KK;
    __shared__ float ps[8][64];
    __shared__ float sMu[CC * CC];
    int t = threadIdx.x, lane = t & 31, g = t >> 5;
    for (int i = t; i < CC * CC; i += 256) sMu[i] = mu[i];
    float a0 = 0.f, a1 = 0.f;
    int j0 = g * 128;
    for (int j = j0; j < j0 + 128; j++) {
        float q = Qb[j * CC + lane];
        a0 = fmaf(eb[j * 2],     q, a0);
        a1 = fmaf(eb[j * 2 + 1], q, a1);
    }
    ps[g][lane]      = a0;
    ps[g][32 + lane] = a1;
    __syncthreads();
    if (t < 64) {                       // warp 0 -> k=0, warp 1 -> k=1
        float tv = 0.f;
#pragma unroll
        for (int w = 0; w < 8; w++) tv += ps[w][t];
        float cs = 0.f;
#pragma unroll
        for (int i = 0; i < 32; i++) {
            float ti = __shfl_sync(FULLM, tv, i);
            cs = fmaf(ti, sMu[i * 32 + lane], cs);
        }
        g_cs[blockIdx.x * 64 + t] = cs;
    }
}

// ------------- CRF part 2: msg (complement trick, Y recomputed) + softmax ---
__global__ void k_msg(const float* __restrict__ kw, const float* __restrict__ mu, int sel) {
    const float* Qin = qsel(sel);
    float* Qout = qselw(sel ^ 1);
    int warp = threadIdx.x >> 5, lane = threadIdx.x & 31;
    int row  = blockIdx.x * 8 + warp;
    int b    = row >> 10;
    int base = b << 10;
    float z0 = g_cs[b * 64 + lane], z1 = g_cs[b * 64 + 32 + lane];
    unsigned myz = ~g_adjl[row * 32 + lane];          // usually all-zero
    if (__any_sync(FULLM, myz != 0u)) {
        for (int wk = 0; wk < 32; wk++) {
            unsigned bits = __shfl_sync(FULLM, myz, wk);
            while (bits) {
                int t = __ffs(bits) - 1; bits &= bits - 1;
                int j = base + (wk << 5) + t;
                float qj = Qin[j * CC + lane];
                float p = 0.f;
#pragma unroll
                for (int c = 0; c < CC; c++)
                    p += __shfl_sync(FULLM, qj, c) * mu[c * CC + lane];
                z0 -= g_e[j * KK]     * p;
                z1 -= g_e[j * KK + 1] * p;
            }
        }
    }
    float e0 = g_e[row * KK] * kw[0], e1 = g_e[row * KK + 1] * kw[1];
    float logit = (g_unary[row * CC + lane] + e0 * z0 + e1 * z1) * INV_TEMP;
    float m = logit;
#pragma unroll
    for (int o = 16; o; o >>= 1) m = fmaxf(m, __shfl_xor_sync(FULLM, m, o));
    float ex = expf(logit - m);
    float s = ex;
#pragma unroll
    for (int o = 16; o; o >>= 1) s += __shfl_xor_sync(FULLM, s, o);
    Qout[row * CC + lane] = ex / s;
}

// ------------- K7: AQ = adj @ Q, 256x32 tile, 8x4/thread fp32x2 -------------
// (EXACT round-5 body)
__global__ void __launch_bounds__(256, 1) k_AQ_dense(int sel) {
    const float* Qf = qsel(sel);
    extern __shared__ float sm[];
    float* As  = sm;                      // [KC][256]
    float* Bs2 = sm + KC * 256;           // [KC][BSTRIDE_A] duplicated, padded
    int b = blockIdx.y, chunk = blockIdx.x;
    int tid = threadIdx.x;
    int tx = tid & 7, ty = tid >> 3;      // tx: 4 cols, ty: 8 rows
    int rowbase = b * NN + chunk * 256;
    u64 acc[4][4];
#pragma unroll
    for (int i = 0; i < 4; i++)
#pragma unroll
        for (int j = 0; j < 4; j++) acc[i][j] = 0ull;

    const unsigned* abase = g_adjb + (size_t)rowbase * 32;

    for (int kc = 0; kc < 16; kc++) {
        __syncthreads();
        unsigned w0 = abase[(size_t)tid * 32 + kc * 2];
        unsigned w1 = abase[(size_t)tid * 32 + kc * 2 + 1];
#pragma unroll
        for (int bit = 0; bit < 32; bit++) {
            As[bit * 256 + tid]        = (float)((w0 >> bit) & 1);
            As[(32 + bit) * 256 + tid] = (float)((w1 >> bit) & 1);
        }
        {
            const float4* src = (const float4*)(Qf + (size_t)(b * NN + kc * 64) * CC);
#pragma unroll
            for (int q = 0; q < 2; q++) {
                int j = tid + q * 256;               // 512 float4s
                float4 v = src[j];
                int r = j >> 3, c4 = (j & 7) * 4;    // cols c4..c4+3 = one 4-group
                int g = c4 >> 2;
                float* dst = &Bs2[r * BSTRIDE_A + g * BSLOT_A];
                *(float4*)(dst)     = make_float4(v.x, v.x, v.y, v.y);
                *(float4*)(dst + 4) = make_float4(v.z, v.z, v.w, v.w);
            }
        }
        __syncthreads();

#pragma unroll 4
        for (int k = 0; k < KC; k++) {
            float4 a0 = *(const float4*)&As[k * 256 + ty * 8];
            float4 a1 = *(const float4*)&As[k * 256 + ty * 8 + 4];
            u64 ap[4] = { pack2(a0.x, a0.y), pack2(a0.z, a0.w),
                          pack2(a1.x, a1.y), pack2(a1.z, a1.w) };
            const float* bp = &Bs2[k * BSTRIDE_A + tx * BSLOT_A];
            float4 b0 = *(const float4*)(bp);
            float4 b1 = *(const float4*)(bp + 4);
            u64 bq[4] = { pack2(b0.x, b0.y), pack2(b0.z, b0.w),
                          pack2(b1.x, b1.y), pack2(b1.z, b1.w) };
#pragma unroll
            for (int rp = 0; rp < 4; rp++)
#pragma unroll
                for (int c = 0; c < 4; c++)
                    FMA2(acc[rp][c], ap[rp], bq[c]);
        }
    }

#pragma unroll
    for (int rp = 0; rp < 4; rp++) {
        int r0 = rowbase + ty * 8 + rp * 2;
        float o0[4], o1[4];
#pragma unroll
        for (int c = 0; c < 4; c++) unpack2(acc[rp][c], o0[c], o1[c]);
        *(float4*)&g_AQ[(size_t)r0 * CC + tx * 4]       = make_float4(o0[0], o0[1], o0[2], o0[3]);
        *(float4*)&g_AQ[(size_t)(r0 + 1) * CC + tx * 4] = make_float4(o1[0], o1[1], o1[2], o1[3]);
    }
}

// ------------- K8a: pooled outputs, N-split partials ------------------------
__global__ void k_poolp(int sel) {
    const float* Qf = qsel(sel);
    __shared__ float Qs[64 * 32];
    __shared__ float hs[64 * 64];
    __shared__ float Aq[64 * 32];
    int b = blockIdx.x, nc = blockIdx.y;
    int tid = threadIdx.x;                  // 256
    int n0 = b * NN + nc * 64;
    {
        const float4* sq = (const float4*)(Qf   + (size_t)n0 * CC);
        const float4* sh = (const float4*)(g_h  + (size_t)n0 * HH);
        const float4* sa = (const float4*)(g_AQ + (size_t)n0 * CC);
        ((float4*)Qs)[tid] = sq[tid];  ((float4*)Qs)[tid + 256] = sq[tid + 256];
        ((float4*)Aq)[tid] = sa[tid];  ((float4*)Aq)[tid + 256] = sa[tid + 256];
#pragma unroll
        for (int q = 0; q < 4; q++) ((float4*)hs)[tid + q * 256] = sh[tid + q * 256];
    }
    __syncthreads();
    int tx = tid & 15, ty = tid >> 4;
    float xp[2][4] = {};
    float ap[2][2] = {};
    for (int n = 0; n < 64; n++) {
        float q0 = Qs[n * 32 + ty * 2], q1 = Qs[n * 32 + ty * 2 + 1];
        float4 hv = *(const float4*)&hs[n * 64 + tx * 4];
        float a0 = Aq[n * 32 + tx * 2], a1 = Aq[n * 32 + tx * 2 + 1];
        xp[0][0] += q0 * hv.x; xp[0][1] += q0 * hv.y; xp[0][2] += q0 * hv.z; xp[0][3] += q0 * hv.w;
        xp[1][0] += q1 * hv.x; xp[1][1] += q1 * hv.y; xp[1][2] += q1 * hv.z; xp[1][3] += q1 * hv.w;
        ap[0][0] += q0 * a0; ap[0][1] += q0 * a1;
        ap[1][0] += q1 * a0; ap[1][1] += q1 * a1;
    }
    float* dst = g_poolp + ((size_t)b * 16 + nc) * 3072;
#pragma unroll
    for (int cc = 0; cc < 2; cc++) {
#pragma unroll
        for (int c4 = 0; c4 < 4; c4++)
            dst[(ty * 2 + cc) * 64 + tx * 4 + c4] = xp[cc][c4];
#pragma unroll
        for (int a = 0; a < 2; a++)
            dst[2048 + (ty * 2 + cc) * 32 + tx * 2 + a] = ap[cc][a];
    }
}

// ------------- K8b: reduce pooling partials ---------------------------------
__global__ void k_poolred(float* __restrict__ out) {
    int b = blockIdx.x;
    int idx = blockIdx.y * 256 + threadIdx.x;
    float s = 0.f;
    for (int ch = 0; ch < 16; ch++) s += g_poolp[((size_t)b * 16 + ch) * 3072 + idx];
    if (idx < 2048) {
        int c = idx >> 6, hcol = idx & 63;
        out[((size_t)b * CC + c) * HH + hcol] = s;
    } else {
        int j = idx - 2048, c = j >> 5, a = j & 31;
        out[(size_t)BB * CC * HH + ((size_t)b * CC + c) * CC + a] = s;
    }
}

// ---------------------------------------------------------------------------
extern "C" void kernel_launch(void* const* d_in, const int* in_sizes, int n_in,
                              void* d_out, int out_size) {
    const float* x      = (const float*)d_in[0];
    const int*   adj    = (const int*)  d_in[1];
    const float* Wg     = (const float*)d_in[2];
    const float* bg     = (const float*)d_in[3];
    const float* Wu     = (const float*)d_in[4];
    const float* bu     = (const float*)d_in[5];
    const float* means  = (const float*)d_in[6];
    const float* scales = (const float*)d_in[7];
    const float* kw     = (const float*)d_in[8];
    const float* mu     = (const float*)d_in[9];
    float* out = (float*)d_out;

    const int SMG = (KC * 256 + KC * BSTRIDE_G) * 4;   // 106496 B
    const int SMA = (KC * 256 + KC * BSTRIDE_A) * 4;   //  90112 B
    cudaFuncSetAttribute(k_gcnagg_dense, cudaFuncAttributeMaxDynamicSharedMemorySize, SMG);
    cudaFuncSetAttribute(k_AQ_dense,     cudaFuncAttributeMaxDynamicSharedMemorySize, SMA);

    k_bits        <<<ROWS / 8,  256>>>(adj);
    k_xw          <<<ROWS / 32, 256>>>(x, Wg);
    k_adjl        <<<ROWS / 8,  256>>>();
    k_gcnagg_dense<<<dim3(4, BB), 256, SMG>>>(bg);
    k_unary_e     <<<ROWS / 8,  256>>>(Wu, bu, means, scales);

    int sel = 0;
    for (int it = 0; it < NITER; it++) {
        k_cs2 <<<BB,       256>>>(mu, sel);
        k_msg <<<ROWS / 8, 256>>>(kw, mu, sel);
        sel ^= 1;
    }

    k_AQ_dense <<<dim3(4, BB), 256, SMA>>>(sel);
    k_poolp    <<<dim3(BB, 16), 256>>>(sel);
    k_poolred  <<<dim3(BB, 12), 256>>>(out);
}

// round 9
// speedup vs baseline: 1.3797x; 1.0499x over previous
#include <cuda_runtime.h>
#include <cuda_bf16.h>
#include <mma.h>

using namespace nvcuda;

#define BB 32
#define NN 1024
#define FF 128
#define HH 64
#define CC 32
#define KK 2
#define NITER 5
#define INV_TEMP 2.0f
#define ROWS (BB*NN)
#define FULLM 0xffffffffu

// WMMA tiling (family-portable HMMA; no sm_103a-gated instructions)
#define TM 256          // rows per block
#define LDA 72          // bf16 elems (144B, mult of 16B)
#define LDB 72
#define LDC_G 72        // f32 elems (288B)
#define LDC_A 40        // f32 elems (160B)
#define SMEM_WG (TM*LDC_G*4)                 // 73728 (Cs alias dominates)
#define SMEM_WA ((TM*LDA + 2*32*LDB) * 2)    // 46080

__device__ __forceinline__ unsigned short f2bf(float f) {
    return __bfloat16_as_ushort(__float2bfloat16(f));
}

// ---------------- scratch (device globals; allocation-free) ----------------
__device__ float          g_dY[ROWS*HH];
__device__ float          g_dinv[ROWS];
__device__ unsigned       g_adjb[ROWS*32];
__device__ unsigned       g_adjl[ROWS*32];
__device__ float          g_h[ROWS*HH];
__device__ float          g_unary[ROWS*CC];
__device__ float          g_e[ROWS*KK];
__device__ float          g_Qa[ROWS*CC];
__device__ float          g_Qb[ROWS*CC];
__device__ float          g_cs[BB*64];
__device__ float          g_AQ[ROWS*CC];
__device__ float          g_poolp[(size_t)BB*16*3072];
__device__ unsigned short g_dYT_hi[(size_t)BB*64*NN];   // [b][c][n] bf16
__device__ unsigned short g_dYT_lo[(size_t)BB*64*NN];
__device__ unsigned short g_QT_hi[(size_t)BB*32*NN];
__device__ unsigned short g_QT_lo[(size_t)BB*32*NN];

__device__ __forceinline__ const float* qsel(int s) { return s ? g_Qb : g_Qa; }
__device__ __forceinline__ float*       qselw(int s){ return s ? g_Qb : g_Qa; }

// ------------- K1: pack adjacency bits + degree -> dinv ---------------------
__global__ void k_bits(const int* __restrict__ adj) {
    int warp = threadIdx.x >> 5, lane = threadIdx.x & 31;
    int row  = blockIdx.x * 8 + warp;
    const int* ar = adj + (size_t)row * NN;
    unsigned myw = 0;
#pragma unroll
    for (int w = 0; w < 32; w++) {
        unsigned bal = __ballot_sync(FULLM, ar[(w << 5) + lane] != 0);
        if (lane == w) myw = bal;
    }
    g_adjb[row * 32 + lane] = myw;
    int d = __popc(myw);
#pragma unroll
    for (int o = 16; o; o >>= 1) d += __shfl_xor_sync(FULLM, d, o);
    if (lane == 0) g_dinv[row] = rsqrtf((float)d + 1.0f);
}

// ------------- K2: xw = x @ W_gcn, scaled by dinv; + transposed bf16 split --
__global__ void k_xw(const float* __restrict__ x, const float* __restrict__ Wg) {
    __shared__ float Ws[FF * HH];
    for (int i = threadIdx.x; i < FF * HH; i += 256) Ws[i] = Wg[i];
    __syncthreads();
    int warp = threadIdx.x >> 5, lane = threadIdx.x & 31;
    for (int r = 0; r < 4; r++) {
        int row = blockIdx.x * 32 + warp * 4 + r;
        const float* xr = x + (size_t)row * FF;
        float a0 = 0.f, a1 = 0.f;
        for (int kb = 0; kb < FF; kb += 32) {
            float xv32 = xr[kb + lane];
#pragma unroll
            for (int t = 0; t < 32; t++) {
                float xv = __shfl_sync(FULLM, xv32, t);
                a0 += xv * Ws[(kb + t) * HH + lane];
                a1 += xv * Ws[(kb + t) * HH + lane + 32];
            }
        }
        float di = g_dinv[row];
        float v0 = a0 * di, v1 = a1 * di;
        g_dY[(size_t)row * HH + lane]      = v0;
        g_dY[(size_t)row * HH + lane + 32] = v1;
        int b = row >> 10, n = row & 1023;
        unsigned short h0 = f2bf(v0);
        unsigned short h1 = f2bf(v1);
        size_t i0 = ((size_t)b * 64 + lane) * NN + n;
        size_t i1 = ((size_t)b * 64 + lane + 32) * NN + n;
        g_dYT_hi[i0] = h0;
        g_dYT_lo[i0] = f2bf(v0 - __bfloat162float(__ushort_as_bfloat16(h0)));
        g_dYT_hi[i1] = h1;
        g_dYT_lo[i1] = f2bf(v1 - __bfloat162float(__ushort_as_bfloat16(h1)));
    }
}

// ------------- K3: 2-hop reachability bitsets -------------------------------
__global__ void k_adjl() {
    int warp = threadIdx.x >> 5, lane = threadIdx.x & 31;
    int row  = blockIdx.x * 8 + warp;
    int base = (row >> 10) << 10;
    unsigned myw = g_adjb[row * 32 + lane];
    unsigned acc = 0;
    for (int wk = 0; wk < 32; wk++) {
        unsigned bits = __shfl_sync(FULLM, myw, wk);
        while (bits) {
            int t = __ffs(bits) - 1; bits &= bits - 1;
            acc |= g_adjb[(size_t)(base + (wk << 5) + t) * 32 + lane];
        }
        if (__all_sync(FULLM, acc == FULLM)) break;
    }
    g_adjl[row * 32 + lane] = acc;
}

// ------------- helper: expand 64 adjacency bits into a bf16 smem row --------
__device__ __forceinline__ void expand_row(__nv_bfloat16* As, int t, unsigned w0, unsigned w1) {
    uint4* dst = (uint4*)(As + t * LDA);
#pragma unroll
    for (int seg = 0; seg < 8; seg++) {
        unsigned byte = ((seg < 4) ? (w0 >> (seg * 8)) : (w1 >> ((seg - 4) * 8))) & 0xFFu;
        uint4 v;
        v.x = ((byte & 1u)  ? 0x3F80u : 0u) | ((byte & 2u)   ? 0x3F800000u : 0u);
        v.y = ((byte & 4u)  ? 0x3F80u : 0u) | ((byte & 8u)   ? 0x3F800000u : 0u);
        v.z = ((byte & 16u) ? 0x3F80u : 0u) | ((byte & 32u)  ? 0x3F800000u : 0u);
        v.w = ((byte & 64u) ? 0x3F80u : 0u) | ((byte & 128u) ? 0x3F800000u : 0u);
        dst[seg] = v;
    }
}

// ------------- K4: GCN aggregate via WMMA bf16 hi+lo split ------------------
// D[256,64] = A_bits[256,1024] @ dY[1024,64]; h = relu(dinv*(D+dY_i)+bias)
__global__ void __launch_bounds__(256, 1) k_gcn_wmma(const float* __restrict__ bg) {
    extern __shared__ char smem[];
    __nv_bfloat16* As  = (__nv_bfloat16*)smem;            // [256][LDA]
    __nv_bfloat16* Bhi = As + TM * LDA;                   // [64][LDB]
    __nv_bfloat16* Blo = Bhi + 64 * LDB;
    float* Cs = (float*)smem;                             // alias (epilogue)

    int t = threadIdx.x, w = t >> 5;
    int wm = w & 3, wn = w >> 2;          // wm: 4x64 rows, wn: 2x32 cols
    int rowbase = blockIdx.x * TM;
    int b = blockIdx.x >> 2;

    wmma::fragment<wmma::accumulator, 16, 16, 16, float> acc[4][2];
#pragma unroll
    for (int i = 0; i < 4; i++)
#pragma unroll
        for (int j = 0; j < 2; j++) wmma::fill_fragment(acc[i][j], 0.0f);

    const unsigned* arow = g_adjb + (size_t)(rowbase + t) * 32;
    const unsigned short* ph = g_dYT_hi + (size_t)b * 64 * NN;
    const unsigned short* pl = g_dYT_lo + (size_t)b * 64 * NN;

    unsigned nw0 = arow[0], nw1 = arow[1];
    uint4 nbh[2], nbl[2];
#pragma unroll
    for (int q = 0; q < 2; q++) {
        int j = t + q * 256, c = j >> 3, seg = j & 7;
        size_t go = (size_t)c * NN + seg * 8;
        nbh[q] = *(const uint4*)(ph + go);
        nbl[q] = *(const uint4*)(pl + go);
    }

    for (int kc = 0; kc < 16; kc++) {
        unsigned w0 = nw0, w1 = nw1;
        uint4 bh[2] = { nbh[0], nbh[1] }, bl[2] = { nbl[0], nbl[1] };
        __syncthreads();
        expand_row(As, t, w0, w1);
#pragma unroll
        for (int q = 0; q < 2; q++) {
            int j = t + q * 256, c = j >> 3, seg = j & 7;
            *(uint4*)(Bhi + c * LDB + seg * 8) = bh[q];
            *(uint4*)(Blo + c * LDB + seg * 8) = bl[q];
        }
        if (kc < 15) {
            nw0 = arow[(kc + 1) * 2];
            nw1 = arow[(kc + 1) * 2 + 1];
#pragma unroll
            for (int q = 0; q < 2; q++) {
                int j = t + q * 256, c = j >> 3, seg = j & 7;
                size_t go = (size_t)c * NN + (kc + 1) * 64 + seg * 8;
                nbh[q] = *(const uint4*)(ph + go);
                nbl[q] = *(const uint4*)(pl + go);
            }
        }
        __syncthreads();

#pragma unroll
        for (int kt = 0; kt < 4; kt++) {
            wmma::fragment<wmma::matrix_a, 16, 16, 16, __nv_bfloat16, wmma::row_major> af[4];
#pragma unroll
            for (int i = 0; i < 4; i++)
                wmma::load_matrix_sync(af[i], As + (wm * 64 + i * 16) * LDA + kt * 16, LDA);
#pragma unroll
            for (int j = 0; j < 2; j++) {
                wmma::fragment<wmma::matrix_b, 16, 16, 16, __nv_bfloat16, wmma::col_major> bfh, bfl;
                wmma::load_matrix_sync(bfh, Bhi + (wn * 32 + j * 16) * LDB + kt * 16, LDB);
                wmma::load_matrix_sync(bfl, Blo + (wn * 32 + j * 16) * LDB + kt * 16, LDB);
#pragma unroll
                for (int i = 0; i < 4; i++) {
                    wmma::mma_sync(acc[i][j], af[i], bfh, acc[i][j]);
                    wmma::mma_sync(acc[i][j], af[i], bfl, acc[i][j]);
                }
            }
        }
    }

    __syncthreads();   // done reading As/Bs; Cs aliases them
#pragma unroll
    for (int i = 0; i < 4; i++)
#pragma unroll
        for (int j = 0; j < 2; j++)
            wmma::store_matrix_sync(Cs + (wm * 64 + i * 16) * LDC_G + (wn * 32 + j * 16),
                                    acc[i][j], LDC_G, wmma::mem_row_major);
    __syncthreads();

    int r = rowbase + t;
    float di = g_dinv[r];
    const float4* dyr = (const float4*)&g_dY[(size_t)r * HH];
    float4* hr = (float4*)&g_h[(size_t)r * HH];
#pragma unroll
    for (int i = 0; i < 16; i++) {
        float4 s = dyr[i];
        float4 o;
        o.x = fmaxf(fmaf(Cs[t * LDC_G + 4*i+0] + s.x, di, bg[4*i+0]), 0.f);
        o.y = fmaxf(fmaf(Cs[t * LDC_G + 4*i+1] + s.y, di, bg[4*i+1]), 0.f);
        o.z = fmaxf(fmaf(Cs[t * LDC_G + 4*i+2] + s.z, di, bg[4*i+2]), 0.f);
        o.w = fmaxf(fmaf(Cs[t * LDC_G + 4*i+3] + s.w, di, bg[4*i+3]), 0.f);
        hr[i] = o;
    }
}

// ------------- K5: unary + e + initial softmax ------------------------------
__global__ void k_unary_e(const float* __restrict__ Wu, const float* __restrict__ bu,
                          const float* __restrict__ means, const float* __restrict__ scales) {
    __shared__ float sW[HH * CC];
    __shared__ float sM[KK * HH], sS[KK * HH];
    for (int i = threadIdx.x; i < HH * CC; i += 256) sW[i] = Wu[i];
    for (int i = threadIdx.x; i < KK * HH; i += 256) { sM[i] = means[i]; sS[i] = scales[i]; }
    __syncthreads();
    int warp = threadIdx.x >> 5, lane = threadIdx.x & 31;
    int row  = blockIdx.x * 8 + warp;
    float h0 = g_h[(size_t)row * HH + lane];
    float h1 = g_h[(size_t)row * HH + lane + 32];
    float acc = bu[lane];
#pragma unroll
    for (int hh = 0; hh < HH; hh++) {
        float hv = __shfl_sync(FULLM, (hh < 32) ? h0 : h1, hh & 31);
        acc += hv * sW[hh * CC + lane];
    }
    g_unary[row * CC + lane] = acc;
#pragma unroll
    for (int k = 0; k < KK; k++) {
        float d0 = (h0 - sM[k * HH + lane])      / sS[k * HH + lane];
        float d1 = (h1 - sM[k * HH + lane + 32]) / sS[k * HH + lane + 32];
        float s = d0 * d0 + d1 * d1;
#pragma unroll
        for (int o = 16; o; o >>= 1) s += __shfl_xor_sync(FULLM, s, o);
        s = __shfl_sync(FULLM, s, 0);
        if (lane == 0) g_e[row * KK + k] = expf(-s);
    }
    float m = acc;
#pragma unroll
    for (int o = 16; o; o >>= 1) m = fmaxf(m, __shfl_xor_sync(FULLM, m, o));
    float ex = expf(acc - m);
    float s = ex;
#pragma unroll
    for (int o = 16; o; o >>= 1) s += __shfl_xor_sync(FULLM, s, o);
    g_Qa[row * CC + lane] = ex / s;
}

// ------------- CRF part 1: cs[k][c] = (sum_j e_jk Q_j) @ mu ------------------
__global__ void k_cs2(const float* __restrict__ mu, int sel) {
    const float* Qb = qsel(sel) + (size_t)blockIdx.x * NN * CC;
    const float* eb = g_e       + (size_t)blockIdx.x * NN * KK;
    __shared__ float ps[8][64];
    __shared__ float sMu[CC * CC];
    int t = threadIdx.x, lane = t & 31, g = t >> 5;
    for (int i = t; i < CC * CC; i += 256) sMu[i] = mu[i];
    float a0 = 0.f, a1 = 0.f;
    int j0 = g * 128;
    for (int j = j0; j < j0 + 128; j++) {
        float q = Qb[j * CC + lane];
        a0 = fmaf(eb[j * 2],     q, a0);
        a1 = fmaf(eb[j * 2 + 1], q, a1);
    }
    ps[g][lane]      = a0;
    ps[g][32 + lane] = a1;
    __syncthreads();
    if (t < 64) {
        float tv = 0.f;
#pragma unroll
        for (int w = 0; w < 8; w++) tv += ps[w][t];
        float cs = 0.f;
#pragma unroll
        for (int i = 0; i < 32; i++) {
            float ti = __shfl_sync(FULLM, tv, i);
            cs = fmaf(ti, sMu[i * 32 + lane], cs);
        }
        g_cs[blockIdx.x * 64 + t] = cs;
    }
}

// ------------- CRF part 2: msg (complement trick) + softmax ------------------
__global__ void k_msg(const float* __restrict__ kw, const float* __restrict__ mu, int sel) {
    const float* Qin = qsel(sel);
    float* Qout = qselw(sel ^ 1);
    int warp = threadIdx.x >> 5, lane = threadIdx.x & 31;
    int row  = blockIdx.x * 8 + warp;
    int b    = row >> 10;
    int base = b << 10;
    float z0 = g_cs[b * 64 + lane], z1 = g_cs[b * 64 + 32 + lane];
    unsigned myz = ~g_adjl[row * 32 + lane];
    if (__any_sync(FULLM, myz != 0u)) {
        for (int wk = 0; wk < 32; wk++) {
            unsigned bits = __shfl_sync(FULLM, myz, wk);
            while (bits) {
                int t = __ffs(bits) - 1; bits &= bits - 1;
                int j = base + (wk << 5) + t;
                float qj = Qin[j * CC + lane];
                float p = 0.f;
#pragma unroll
                for (int c = 0; c < CC; c++)
                    p += __shfl_sync(FULLM, qj, c) * mu[c * CC + lane];
                z0 -= g_e[j * KK]     * p;
                z1 -= g_e[j * KK + 1] * p;
            }
        }
    }
    float e0 = g_e[row * KK] * kw[0], e1 = g_e[row * KK + 1] * kw[1];
    float logit = (g_unary[row * CC + lane] + e0 * z0 + e1 * z1) * INV_TEMP;
    float m = logit;
#pragma unroll
    for (int o = 16; o; o >>= 1) m = fmaxf(m, __shfl_xor_sync(FULLM, m, o));
    float ex = expf(logit - m);
    float s = ex;
#pragma unroll
    for (int o = 16; o; o >>= 1) s += __shfl_xor_sync(FULLM, s, o);
    Qout[row * CC + lane] = ex / s;
}

// ------------- K6b: transpose+split final Q -> QT hi/lo ---------------------
__global__ void k_qt(int sel) {
    const float* Q = qsel(sel) + (size_t)blockIdx.x * NN * CC;
    int b = blockIdx.x;
    for (int i = threadIdx.x; i < NN * CC; i += 256) {
        int n = i >> 5, c = i & 31;
        float v = Q[i];
        unsigned short h = f2bf(v);
        size_t o = ((size_t)b * 32 + c) * NN + n;
        g_QT_hi[o] = h;
        g_QT_lo[o] = f2bf(v - __bfloat162float(__ushort_as_bfloat16(h)));
    }
}

// ------------- K7: AQ = adj @ Q via WMMA bf16 hi+lo split -------------------
__global__ void __launch_bounds__(256, 1) k_aq_wmma() {
    extern __shared__ char smem[];
    __nv_bfloat16* As  = (__nv_bfloat16*)smem;            // [256][LDA]
    __nv_bfloat16* Bhi = As + TM * LDA;                   // [32][LDB]
    __nv_bfloat16* Blo = Bhi + 32 * LDB;
    float* Cs = (float*)smem;                             // alias (epilogue)

    int t = threadIdx.x, w = t >> 5;
    int wm = w & 3, wn = w >> 2;          // wm: 4x64 rows, wn: 2x16 cols
    int rowbase = blockIdx.x * TM;
    int b = blockIdx.x >> 2;

    wmma::fragment<wmma::accumulator, 16, 16, 16, float> acc[4];
#pragma unroll
    for (int i = 0; i < 4; i++) wmma::fill_fragment(acc[i], 0.0f);

    const unsigned* arow = g_adjb + (size_t)(rowbase + t) * 32;
    const unsigned short* ph = g_QT_hi + (size_t)b * 32 * NN;
    const unsigned short* pl = g_QT_lo + (size_t)b * 32 * NN;

    unsigned nw0 = arow[0], nw1 = arow[1];
    uint4 nbh, nbl;
    {
        int c = t >> 3, seg = t & 7;
        size_t go = (size_t)c * NN + seg * 8;
        nbh = *(const uint4*)(ph + go);
        nbl = *(const uint4*)(pl + go);
    }

    for (int kc = 0; kc < 16; kc++) {
        unsigned w0 = nw0, w1 = nw1;
        uint4 bh = nbh, bl = nbl;
        __syncthreads();
        expand_row(As, t, w0, w1);
        {
            int c = t >> 3, seg = t & 7;
            *(uint4*)(Bhi + c * LDB + seg * 8) = bh;
            *(uint4*)(Blo + c * LDB + seg * 8) = bl;
        }
        if (kc < 15) {
            nw0 = arow[(kc + 1) * 2];
            nw1 = arow[(kc + 1) * 2 + 1];
            int c = t >> 3, seg = t & 7;
            size_t go = (size_t)c * NN + (kc + 1) * 64 + seg * 8;
            nbh = *(const uint4*)(ph + go);
            nbl = *(const uint4*)(pl + go);
        }
        __syncthreads();

#pragma unroll
        for (int kt = 0; kt < 4; kt++) {
            wmma::fragment<wmma::matrix_a, 16, 16, 16, __nv_bfloat16, wmma::row_major> af[4];
#pragma unroll
            for (int i = 0; i < 4; i++)
                wmma::load_matrix_sync(af[i], As + (wm * 64 + i * 16) * LDA + kt * 16, LDA);
            wmma::fragment<wmma::matrix_b, 16, 16, 16, __nv_bfloat16, wmma::col_major> bfh, bfl;
            wmma::load_matrix_sync(bfh, Bhi + (wn * 16) * LDB + kt * 16, LDB);
            wmma::load_matrix_sync(bfl, Blo + (wn * 16) * LDB + kt * 16, LDB);
#pragma unroll
            for (int i = 0; i < 4; i++) {
                wmma::mma_sync(acc[i], af[i], bfh, acc[i]);
                wmma::mma_sync(acc[i], af[i], bfl, acc[i]);
            }
        }
    }

    __syncthreads();
#pragma unroll
    for (int i = 0; i < 4; i++)
        wmma::store_matrix_sync(Cs + (wm * 64 + i * 16) * LDC_A + wn * 16,
                                acc[i], LDC_A, wmma::mem_row_major);
    __syncthreads();

    int r = rowbase + t;
    float4* ar = (float4*)&g_AQ[(size_t)r * CC];
#pragma unroll
    for (int i = 0; i < 8; i++)
        ar[i] = make_float4(Cs[t * LDC_A + 4*i+0], Cs[t * LDC_A + 4*i+1],
                            Cs[t * LDC_A + 4*i+2], Cs[t * LDC_A + 4*i+3]);
}

// ------------- K8a: pooled outputs, N-split partials ------------------------
__global__ void k_poolp(int sel) {
    const float* Qf = qsel(sel);
    __shared__ float Qs[64 * 32];
    __shared__ float hs[64 * 64];
    __shared__ float Aq[64 * 32];
    int b = blockIdx.x, nc = blockIdx.y;
    int tid = threadIdx.x;
    int n0 = b * NN + nc * 64;
    {
        const float4* sq = (const float4*)(Qf   + (size_t)n0 * CC);
        const float4* sh = (const float4*)(g_h  + (size_t)n0 * HH);
        const float4* sa = (const float4*)(g_AQ + (size_t)n0 * CC);
        ((float4*)Qs)[tid] = sq[tid];  ((float4*)Qs)[tid + 256] = sq[tid + 256];
        ((float4*)Aq)[tid] = sa[tid];  ((float4*)Aq)[tid + 256] = sa[tid + 256];
#pragma unroll
        for (int q = 0; q < 4; q++) ((float4*)hs)[tid + q * 256] = sh[tid + q * 256];
    }
    __syncthreads();
    int tx = tid & 15, ty = tid >> 4;
    float xp[2][4] = {};
    float ap[2][2] = {};
    for (int n = 0; n < 64; n++) {
        float q0 = Qs[n * 32 + ty * 2], q1 = Qs[n * 32 + ty * 2 + 1];
        float4 hv = *(const float4*)&hs[n * 64 + tx * 4];
        float a0 = Aq[n * 32 + tx * 2], a1 = Aq[n * 32 + tx * 2 + 1];
        xp[0][0] += q0 * hv.x; xp[0][1] += q0 * hv.y; xp[0][2] += q0 * hv.z; xp[0][3] += q0 * hv.w;
        xp[1][0] += q1 * hv.x; xp[1][1] += q1 * hv.y; xp[1][2] += q1 * hv.z; xp[1][3] += q1 * hv.w;
        ap[0][0] += q0 * a0; ap[0][1] += q0 * a1;
        ap[1][0] += q1 * a0; ap[1][1] += q1 * a1;
    }
    float* dst = g_poolp + ((size_t)b * 16 + nc) * 3072;
#pragma unroll
    for (int cc = 0; cc < 2; cc++) {
#pragma unroll
        for (int c4 = 0; c4 < 4; c4++)
            dst[(ty * 2 + cc) * 64 + tx * 4 + c4] = xp[cc][c4];
#pragma unroll
        for (int a = 0; a < 2; a++)
            dst[2048 + (ty * 2 + cc) * 32 + tx * 2 + a] = ap[cc][a];
    }
}

// ------------- K8b: reduce pooling partials ---------------------------------
__global__ void k_poolred(float* __restrict__ out) {
    int b = blockIdx.x;
    int idx = blockIdx.y * 256 + threadIdx.x;
    float s = 0.f;
    for (int ch = 0; ch < 16; ch++) s += g_poolp[((size_t)b * 16 + ch) * 3072 + idx];
    if (idx < 2048) {
        int c = idx >> 6, hcol = idx & 63;
        out[((size_t)b * CC + c) * HH + hcol] = s;
    } else {
        int j = idx - 2048, c = j >> 5, a = j & 31;
        out[(size_t)BB * CC * HH + ((size_t)b * CC + c) * CC + a] = s;
    }
}

// ---------------------------------------------------------------------------
extern "C" void kernel_launch(void* const* d_in, const int* in_sizes, int n_in,
                              void* d_out, int out_size) {
    const float* x      = (const float*)d_in[0];
    const int*   adj    = (const int*)  d_in[1];
    const float* Wg     = (const float*)d_in[2];
    const float* bg     = (const float*)d_in[3];
    const float* Wu     = (const float*)d_in[4];
    const float* bu     = (const float*)d_in[5];
    const float* means  = (const float*)d_in[6];
    const float* scales = (const float*)d_in[7];
    const float* kw     = (const float*)d_in[8];
    const float* mu     = (const float*)d_in[9];
    float* out = (float*)d_out;

    cudaFuncSetAttribute(k_gcn_wmma, cudaFuncAttributeMaxDynamicSharedMemorySize, SMEM_WG);
    cudaFuncSetAttribute(k_aq_wmma,  cudaFuncAttributeMaxDynamicSharedMemorySize, SMEM_WA);

    k_bits     <<<ROWS / 8,  256>>>(adj);
    k_xw       <<<ROWS / 32, 256>>>(x, Wg);
    k_adjl     <<<ROWS / 8,  256>>>();
    k_gcn_wmma <<<ROWS / TM, 256, SMEM_WG>>>(bg);
    k_unary_e  <<<ROWS / 8,  256>>>(Wu, bu, means, scales);

    int sel = 0;
    for (int it = 0; it < NITER; it++) {
        k_cs2 <<<BB,       256>>>(mu, sel);
        k_msg <<<ROWS / 8, 256>>>(kw, mu, sel);
        sel ^= 1;
    }

    k_qt      <<<BB, 256>>>(sel);
    k_aq_wmma <<<ROWS / TM, 256, SMEM_WA>>>();
    k_poolp   <<<dim3(BB, 16), 256>>>(sel);
    k_poolred <<<dim3(BB, 12), 256>>>(out);
}